// round 1
// baseline (speedup 1.0000x reference)
#include <cuda_runtime.h>
#include <math.h>

// Problem shape constants
constexpr int SEQ  = 2048;
constexpr int DIM  = 4096;
constexpr int NH   = 32;
constexpr int NKV  = 8;
constexpr int HDIM = 128;

// Scratch (device globals: allocation-free rule)
__device__ float g_Q[SEQ * NH * HDIM];     // 32 MB
__device__ float g_K[SEQ * NKV * HDIM];    // 8 MB
__device__ float g_V[SEQ * NKV * HDIM];    // 8 MB
__device__ float g_CTX[SEQ * NH * HDIM];   // 32 MB

// ---------------------------------------------------------------------------
// Fast exp on the FMA pipe (avoids MUFU bottleneck: 67M exps in softmax).
// exp(x) = 2^(x*log2e); x <= 0 always here. Degree-6 Taylor of 2^f, f in [0,1).
// Max rel error ~1.5e-5.
// ---------------------------------------------------------------------------
__device__ __forceinline__ float fexp(float x) {
    float y = x * 1.4426950408889634f;
    y = fmaxf(y, -125.0f);
    float fl = floorf(y);
    float t = y - fl;
    float r = 1.5403530e-4f;
    r = fmaf(r, t, 1.3333558e-3f);
    r = fmaf(r, t, 9.6181291e-3f);
    r = fmaf(r, t, 5.5504109e-2f);
    r = fmaf(r, t, 2.4022651e-1f);
    r = fmaf(r, t, 6.9314718e-1f);
    r = fmaf(r, t, 1.0f);
    float s = __int_as_float(((int)fl + 127) << 23);
    return r * s;
}

// ---------------------------------------------------------------------------
// fp32 tiled GEMM: C[m0:+128, n0:+128] = A[M,K] @ B[K,N] (row-major).
// 256 threads, 8x8 micro-tile, BK=16, A staged transposed in smem.
// ---------------------------------------------------------------------------
__device__ __forceinline__ void gemm_tile_128(
    const float* __restrict__ A, const float* __restrict__ B,
    float* __restrict__ C, int K, int N, int m0, int n0)
{
    __shared__ float As[16][128];
    __shared__ float Bs[16][128];

    const int tid  = threadIdx.x;
    const int tx   = tid & 15;
    const int ty   = tid >> 4;
    const int arow = tid >> 2;          // 0..63
    const int acol = (tid & 3) << 2;    // 0,4,8,12
    const int brow = tid >> 5;          // 0..7
    const int bcol = (tid & 31) << 2;   // 0..124

    float acc[8][8];
#pragma unroll
    for (int i = 0; i < 8; i++)
#pragma unroll
        for (int j = 0; j < 8; j++) acc[i][j] = 0.f;

    for (int k0 = 0; k0 < K; k0 += 16) {
#pragma unroll
        for (int it = 0; it < 2; it++) {
            int r = arow + it * 64;
            float4 v = *(const float4*)(A + (size_t)(m0 + r) * K + k0 + acol);
            As[acol + 0][r] = v.x;
            As[acol + 1][r] = v.y;
            As[acol + 2][r] = v.z;
            As[acol + 3][r] = v.w;
        }
#pragma unroll
        for (int it = 0; it < 2; it++) {
            int r = brow + it * 8;
            *(float4*)(&Bs[r][bcol]) =
                *(const float4*)(B + (size_t)(k0 + r) * N + n0 + bcol);
        }
        __syncthreads();

#pragma unroll
        for (int kk = 0; kk < 16; kk++) {
            float a[8], b[8];
            *(float4*)(a)     = *(const float4*)(&As[kk][ty * 8]);
            *(float4*)(a + 4) = *(const float4*)(&As[kk][ty * 8 + 4]);
            *(float4*)(b)     = *(const float4*)(&Bs[kk][tx * 8]);
            *(float4*)(b + 4) = *(const float4*)(&Bs[kk][tx * 8 + 4]);
#pragma unroll
            for (int i = 0; i < 8; i++)
#pragma unroll
                for (int j = 0; j < 8; j++)
                    acc[i][j] = fmaf(a[i], b[j], acc[i][j]);
        }
        __syncthreads();
    }

#pragma unroll
    for (int i = 0; i < 8; i++) {
        float* cp = C + (size_t)(m0 + ty * 8 + i) * N + n0 + tx * 8;
        *(float4*)(cp)     = *(float4*)(&acc[i][0]);
        *(float4*)(cp + 4) = *(float4*)(&acc[i][4]);
    }
}

// Fused QKV projection: one launch covering Q (32 n-tiles), K (8), V (8).
__global__ __launch_bounds__(256, 2)
void qkv_kernel(const float* __restrict__ X,
                const float* __restrict__ wq,
                const float* __restrict__ wk,
                const float* __restrict__ wv)
{
    int nt = blockIdx.x, mt = blockIdx.y;
    const float* B;
    float* C;
    int N, nl;
    if (nt < 32)      { B = wq; C = g_Q; N = NH * HDIM;  nl = nt; }
    else if (nt < 40) { B = wk; C = g_K; N = NKV * HDIM; nl = nt - 32; }
    else              { B = wv; C = g_V; N = NKV * HDIM; nl = nt - 40; }
    gemm_tile_128(X, B, C, DIM, N, mt * 128, nl * 128);
}

// Output projection: out = CTX @ wo
__global__ __launch_bounds__(256, 2)
void out_kernel(const float* __restrict__ wo, float* __restrict__ out)
{
    gemm_tile_128(g_CTX, wo, out, NH * HDIM, DIM,
                  (int)blockIdx.y * 128, (int)blockIdx.x * 128);
}

// ---------------------------------------------------------------------------
// RoPE in-place on g_Q and g_K. One thread per (seq, head, dim<64) pair.
// Mirrors reference fp32 op order: t = float(pos) * float(freq); cos/sin in fp32.
// ---------------------------------------------------------------------------
__global__ void rope_kernel(const int* __restrict__ pos)
{
    int idx = blockIdx.x * blockDim.x + threadIdx.x;
    const int totq = SEQ * NH * 64;
    const int tot  = totq + SEQ * NKV * 64;
    if (idx >= tot) return;

    float* ptr;
    int nh;
    if (idx < totq) { ptr = g_Q; nh = NH; }
    else            { idx -= totq; ptr = g_K; nh = NKV; }

    int i = idx & 63;
    int h = (idx >> 6) % nh;
    int s = idx / (64 * nh);

    float p = (float)pos[s];
    // freq = 1 / theta^(i/64), theta = 1e6; correctly rounded via double exp2
    float freq = (float)exp2(-(double)i * 0.31143075889569021);
    float t = p * freq;
    float sn, c;
    sincosf(t, &sn, &c);

    float* base = ptr + (size_t)s * (nh * HDIM) + h * HDIM + i;
    float x1 = base[0], x2 = base[64];
    base[0]  = x1 * c  - x2 * sn;
    base[64] = x1 * sn + x2 * c;
}

// ---------------------------------------------------------------------------
// Flash attention, fp32, causal + attention_mask, GQA (4 q-heads per kv head).
// One block = (head, 64-row q tile). 256 threads.
// Score phase: 16x16 thread grid, 4x4 micro-tiles, XOR-swizzled smem for
// conflict-free LDS.128 of K fragments. Online softmax with register m/l
// (replicated across the 16 lanes owning each row group; shfl width-16 reduce).
// ---------------------------------------------------------------------------
constexpr int ATTN_SMEM_FLOATS = 8192 * 3 + 4096 + 64; // Qs,Ks,Vs,Ps,msk
constexpr int ATTN_SMEM = ATTN_SMEM_FLOATS * 4;

__global__ __launch_bounds__(256, 1)
void attn_kernel(const float* __restrict__ amask)
{
    extern __shared__ float sm[];
    float* Qs  = sm;            // [64][128], swizzled slots
    float* Ks  = Qs + 8192;     // [64][128], swizzled slots
    float* Vs  = Ks + 8192;     // [64][128], row-major
    float* Ps  = Vs + 8192;     // [64][64]
    float* msk = Ps + 4096;     // [64]

    const int h   = blockIdx.x;
    const int qt  = (int)gridDim.y - 1 - (int)blockIdx.y; // heavy tiles first
    const int g   = h >> 2;
    const int tid = threadIdx.x;
    const int tx  = tid & 15;
    const int ty  = tid >> 4;
    const int q0  = qt * 64;

    const int lrow = tid >> 5;  // 0..7 (load row)
    const int slot = tid & 31;  // float4 slot 0..31

    // Load Q tile (swizzled, pre-scaled by 1/sqrt(128))
    {
        const float scale = 0.08838834764831845f;
#pragma unroll
        for (int it = 0; it < 8; it++) {
            int row = lrow + it * 8;
            float4 v = *(const float4*)(g_Q + (size_t)(q0 + row) * (NH * HDIM)
                                        + h * HDIM + slot * 4);
            v.x *= scale; v.y *= scale; v.z *= scale; v.w *= scale;
            *(float4*)(Qs + row * 128 + ((slot ^ (row & 31)) << 2)) = v;
        }
    }

    float acc[4][8];
#pragma unroll
    for (int r = 0; r < 4; r++)
#pragma unroll
        for (int j = 0; j < 8; j++) acc[r][j] = 0.f;

    float mrow[4], lsum[4];
#pragma unroll
    for (int r = 0; r < 4; r++) { mrow[r] = -1e30f; lsum[r] = 0.f; }

    int qsw[4], ksw[4];
#pragma unroll
    for (int r = 0; r < 4; r++) {
        qsw[r] = (4 * ty + r) & 31;
        ksw[r] = (4 * tx + r) & 31;
    }

    const int nkt = qt + 1;
    for (int kt = 0; kt < nkt; kt++) {
        const int k0 = kt * 64;
        __syncthreads();  // protect Ks/Vs/Ps from previous iteration readers

        // Load K (swizzled) + V (row-major) tiles, and mask slice
#pragma unroll
        for (int it = 0; it < 8; it++) {
            int row = lrow + it * 8;
            size_t goff = (size_t)(k0 + row) * (NKV * HDIM) + g * HDIM + slot * 4;
            float4 kv = *(const float4*)(g_K + goff);
            *(float4*)(Ks + row * 128 + ((slot ^ (row & 31)) << 2)) = kv;
            float4 vv = *(const float4*)(g_V + goff);
            *(float4*)(Vs + row * 128 + slot * 4) = vv;
        }
        if (tid < 64) msk[tid] = amask[k0 + tid];
        __syncthreads();

        // Scores: sc[r][c] = Q[4ty+r] . K[4tx+c]
        float sc[4][4];
#pragma unroll
        for (int r = 0; r < 4; r++)
#pragma unroll
            for (int c = 0; c < 4; c++) sc[r][c] = 0.f;

#pragma unroll 4
        for (int d = 0; d < 32; d++) {
            float4 qv[4], kv[4];
#pragma unroll
            for (int r = 0; r < 4; r++)
                qv[r] = *(const float4*)(Qs + (4 * ty + r) * 128 + ((d ^ qsw[r]) << 2));
#pragma unroll
            for (int c = 0; c < 4; c++)
                kv[c] = *(const float4*)(Ks + (4 * tx + c) * 128 + ((d ^ ksw[c]) << 2));
#pragma unroll
            for (int r = 0; r < 4; r++)
#pragma unroll
                for (int c = 0; c < 4; c++) {
                    sc[r][c] = fmaf(qv[r].x, kv[c].x, sc[r][c]);
                    sc[r][c] = fmaf(qv[r].y, kv[c].y, sc[r][c]);
                    sc[r][c] = fmaf(qv[r].z, kv[c].z, sc[r][c]);
                    sc[r][c] = fmaf(qv[r].w, kv[c].w, sc[r][c]);
                }
        }

        // Mask: attention_mask everywhere; causal only on the diagonal tile
        const bool diag = (kt == qt);
#pragma unroll
        for (int c = 0; c < 4; c++) {
            float bias = (msk[4 * tx + c] > 0.f) ? 0.f : -1e30f;
#pragma unroll
            for (int r = 0; r < 4; r++) {
                float b = bias;
                if (diag && (4 * tx + c) > (4 * ty + r)) b = -1e30f;
                sc[r][c] += b;
            }
        }

        // Online softmax update (row groups = 16 consecutive lanes)
        float alpha[4];
#pragma unroll
        for (int r = 0; r < 4; r++) {
            float mx = fmaxf(fmaxf(sc[r][0], sc[r][1]), fmaxf(sc[r][2], sc[r][3]));
#pragma unroll
            for (int off = 1; off < 16; off <<= 1)
                mx = fmaxf(mx, __shfl_xor_sync(0xffffffffu, mx, off, 16));
            float mnew = fmaxf(mrow[r], mx);
            float ssum = 0.f;
#pragma unroll
            for (int c = 0; c < 4; c++) {
                float p = fexp(sc[r][c] - mnew);
                sc[r][c] = p;
                ssum += p;
            }
#pragma unroll
            for (int off = 1; off < 16; off <<= 1)
                ssum += __shfl_xor_sync(0xffffffffu, ssum, off, 16);
            alpha[r] = fexp(mrow[r] - mnew);
            mrow[r] = mnew;
            lsum[r] = lsum[r] * alpha[r] + ssum;
        }

        // Stage P, rescale accumulators
#pragma unroll
        for (int r = 0; r < 4; r++) {
            float4 pv = make_float4(sc[r][0], sc[r][1], sc[r][2], sc[r][3]);
            *(float4*)(Ps + (4 * ty + r) * 64 + 4 * tx) = pv;
        }
#pragma unroll
        for (int r = 0; r < 4; r++)
#pragma unroll
            for (int j = 0; j < 8; j++) acc[r][j] *= alpha[r];
        __syncthreads();

        // acc += P @ V  (thread owns rows 4ty..+3, cols 8tx..+7)
#pragma unroll 8
        for (int kk = 0; kk < 64; kk++) {
            float4 v0 = *(const float4*)(Vs + kk * 128 + tx * 8);
            float4 v1 = *(const float4*)(Vs + kk * 128 + tx * 8 + 4);
#pragma unroll
            for (int r = 0; r < 4; r++) {
                float p = Ps[(4 * ty + r) * 64 + kk];
                acc[r][0] = fmaf(p, v0.x, acc[r][0]);
                acc[r][1] = fmaf(p, v0.y, acc[r][1]);
                acc[r][2] = fmaf(p, v0.z, acc[r][2]);
                acc[r][3] = fmaf(p, v0.w, acc[r][3]);
                acc[r][4] = fmaf(p, v1.x, acc[r][4]);
                acc[r][5] = fmaf(p, v1.y, acc[r][5]);
                acc[r][6] = fmaf(p, v1.z, acc[r][6]);
                acc[r][7] = fmaf(p, v1.w, acc[r][7]);
            }
        }
    }

    // Normalize and write context
#pragma unroll
    for (int r = 0; r < 4; r++) {
        float inv = 1.0f / lsum[r];
        float4 o0 = make_float4(acc[r][0] * inv, acc[r][1] * inv,
                                acc[r][2] * inv, acc[r][3] * inv);
        float4 o1 = make_float4(acc[r][4] * inv, acc[r][5] * inv,
                                acc[r][6] * inv, acc[r][7] * inv);
        float* cp = g_CTX + (size_t)(q0 + 4 * ty + r) * (NH * HDIM)
                    + h * HDIM + tx * 8;
        *(float4*)(cp)     = o0;
        *(float4*)(cp + 4) = o1;
    }
}

// ---------------------------------------------------------------------------
extern "C" void kernel_launch(void* const* d_in, const int* in_sizes, int n_in,
                              void* d_out, int out_size)
{
    const float* X   = (const float*)d_in[0]; // hidden_states [2048,4096]
    const float* am  = (const float*)d_in[1]; // attention_mask [2048]
    const int*   pos = (const int*)  d_in[2]; // position_ids [2048]
    const float* wq  = (const float*)d_in[3]; // [4096,4096]
    const float* wk  = (const float*)d_in[4]; // [4096,1024]
    const float* wv  = (const float*)d_in[5]; // [4096,1024]
    const float* wo  = (const float*)d_in[6]; // [4096,4096]
    float* out = (float*)d_out;               // [2048,4096]

    (void)in_sizes; (void)n_in; (void)out_size;

    // 1. Fused QKV projection
    qkv_kernel<<<dim3(48, 16), 256>>>(X, wq, wk, wv);

    // 2. RoPE on Q and K
    int tot = SEQ * (NH + NKV) * 64;
    rope_kernel<<<(tot + 255) / 256, 256>>>(pos);

    // 3. Flash attention (dynamic smem > 48KB)
    cudaFuncSetAttribute((const void*)attn_kernel,
                         cudaFuncAttributeMaxDynamicSharedMemorySize, ATTN_SMEM);
    attn_kernel<<<dim3(NH, SEQ / 64), 256, ATTN_SMEM>>>(am);

    // 4. Output projection
    out_kernel<<<dim3(32, 16), 256>>>(wo, out);
}

// round 5
// speedup vs baseline: 1.5583x; 1.5583x over previous
#include <cuda_runtime.h>
#include <cuda_bf16.h>
#include <math.h>
#include <cstdint>

// Problem shape constants
constexpr int SEQ  = 2048;
constexpr int DIM  = 4096;
constexpr int NH   = 32;
constexpr int NKV  = 8;
constexpr int HDIM = 128;

// Scratch (device globals: allocation-free rule)
__device__ float g_Q[SEQ * NH * HDIM];     // 32 MB
__device__ float g_K[SEQ * NKV * HDIM];    // 8 MB
__device__ float g_V[SEQ * NKV * HDIM];    // 8 MB

// Split-bf16 operands (16B-aligned for cp.async)
__device__ __align__(256) __nv_bfloat16 g_Xhi[SEQ * DIM];
__device__ __align__(256) __nv_bfloat16 g_Xlo[SEQ * DIM];
__device__ __align__(256) __nv_bfloat16 g_Wqkvt_hi[6144 * DIM];   // [N=6144][K=4096] = W^T
__device__ __align__(256) __nv_bfloat16 g_Wqkvt_lo[6144 * DIM];
__device__ __align__(256) __nv_bfloat16 g_Wot_hi[DIM * DIM];      // [N=4096][K=4096] = Wo^T
__device__ __align__(256) __nv_bfloat16 g_Wot_lo[DIM * DIM];
__device__ __align__(256) __nv_bfloat16 g_Chi[SEQ * DIM];         // attention out (split)
__device__ __align__(256) __nv_bfloat16 g_Clo[SEQ * DIM];

// ===========================================================================
// PTX helpers (compute_100-baseline only: cp.async / ldmatrix / mma.sync)
// ===========================================================================
__device__ __forceinline__ uint32_t smem_to_u32(const void* smem_ptr) {
    uint32_t addr;
    asm("{ .reg .u64 tmp; cvta.to.shared.u64 tmp, %1; cvt.u32.u64 %0, tmp; }"
        : "=r"(addr) : "l"(smem_ptr));
    return addr;
}
__device__ __forceinline__ void cp16(uint32_t dst, const void* src) {
    asm volatile("cp.async.cg.shared.global [%0], [%1], 16;\n" :: "r"(dst), "l"(src));
}
#define CP_COMMIT() asm volatile("cp.async.commit_group;\n" ::: "memory")
#define CP_WAIT(n)  asm volatile("cp.async.wait_group %0;\n" :: "n"(n) : "memory")

// ALL fragment operands are named scalars — no arrays anywhere near inline asm
// (array-element asm operands defeated SROA -> 512 B/thread local -> 128 MiB
// local-pool growth -> harness mem-delta violation in R3/R4).
#define LDSM_OP(r0, r1, r2, r3, addr) \
    asm volatile("ldmatrix.sync.aligned.m8n8.x4.shared.b16 {%0,%1,%2,%3}, [%4];" \
        : "=r"(r0), "=r"(r1), "=r"(r2), "=r"(r3) : "r"(addr))

#define MMA_OP(d0, d1, d2, d3, A0, A1, A2, A3, B0, B1) \
    asm volatile("mma.sync.aligned.m16n8k16.row.col.f32.bf16.bf16.f32 " \
        "{%0,%1,%2,%3}, {%4,%5,%6,%7}, {%8,%9}, {%0,%1,%2,%3};" \
        : "+f"(d0), "+f"(d1), "+f"(d2), "+f"(d3) \
        : "r"(A0), "r"(A1), "r"(A2), "r"(A3), "r"(B0), "r"(B1))

// ===========================================================================
// Split conversions
// ===========================================================================
__device__ __forceinline__ void split1(float x, __nv_bfloat16& h, __nv_bfloat16& l) {
    h = __float2bfloat16(x);
    l = __float2bfloat16(x - __bfloat162float(h));
}

__global__ void xsplit_kernel(const float* __restrict__ X, int total4) {
    int idx = blockIdx.x * blockDim.x + threadIdx.x;
    if (idx >= total4) return;
    float4 v = ((const float4*)X)[idx];
    __nv_bfloat16 h0, h1, h2, h3, l0, l1, l2, l3;
    split1(v.x, h0, l0); split1(v.y, h1, l1);
    split1(v.z, h2, l2); split1(v.w, h3, l3);
    __nv_bfloat162* H2 = (__nv_bfloat162*)(g_Xhi + (size_t)idx * 4);
    __nv_bfloat162* L2 = (__nv_bfloat162*)(g_Xlo + (size_t)idx * 4);
    H2[0] = __nv_bfloat162(h0, h1); H2[1] = __nv_bfloat162(h2, h3);
    L2[0] = __nv_bfloat162(l0, l1); L2[1] = __nv_bfloat162(l2, l3);
}

// Transpose + split: W [K=4096, N] -> T[hi/lo] [dst_row_off + n, k]
__global__ void wsplit_t_kernel(const float* __restrict__ W, int N,
                                int dst_row_off, int which) { // 0 -> Wqkvt, 1 -> Wot
    __shared__ float s[32][33];
    int n0 = blockIdx.x * 32, k0 = blockIdx.y * 32;
    int lx = threadIdx.x & 31, ly = threadIdx.x >> 5;  // ly 0..7
#pragma unroll
    for (int r = 0; r < 4; r++) {
        int row = ly + r * 8;
        s[row][lx] = W[(size_t)(k0 + row) * N + n0 + lx];
    }
    __syncthreads();
    __nv_bfloat16* Hi = which ? g_Wot_hi : g_Wqkvt_hi;
    __nv_bfloat16* Lo = which ? g_Wot_lo : g_Wqkvt_lo;
#pragma unroll
    for (int r = 0; r < 4; r++) {
        int nrow = ly + r * 8;
        float x = s[lx][nrow];  // = W[k0+lx][n0+nrow]
        __nv_bfloat16 h, l; split1(x, h, l);
        size_t o = (size_t)(dst_row_off + n0 + nrow) * DIM + k0 + lx;
        Hi[o] = h; Lo[o] = l;
    }
}

// ===========================================================================
// HMMA split-bf16 GEMM: C[128,128] = (Ahi+Alo)[128,4096] @ (Bhi+Blo)^T
// Block 128x128x32, 8 warps (2x4), 3-stage cp.async pipeline. smem row =
// 32 bf16 = 4 x 16B chunks, swizzle chunk ^= (row>>1)&3.
// ===========================================================================
constexpr int GSTAGES   = 3;
constexpr int GSTG_B    = 32768;               // 4 buffers x 8KB
constexpr int GEMM_SMEM = GSTAGES * GSTG_B;    // 96 KB

__device__ __forceinline__ uint32_t sw_off(int row, int chunk) {
    return (uint32_t)(row * 64 + ((chunk ^ ((row >> 1) & 3)) << 4));
}

__device__ __forceinline__ void load_buf(uint32_t dbase, const __nv_bfloat16* g,
                                         int k0, int tid) {
#pragma unroll
    for (int j = 0; j < 2; j++) {
        int c   = tid * 2 + j;          // 0..511
        int row = c >> 2, ch = c & 3;
        cp16(dbase + sw_off(row, ch), g + (size_t)row * DIM + k0 + ch * 8);
    }
}

__device__ __forceinline__ void g_load_stage(
    uint32_t sbase, int s, int k0,
    const __nv_bfloat16* Ahi, const __nv_bfloat16* Alo,
    const __nv_bfloat16* Bhi, const __nv_bfloat16* Blo, int tid)
{
    uint32_t stbase = sbase + (uint32_t)s * GSTG_B;
    load_buf(stbase,         Ahi, k0, tid);
    load_buf(stbase + 8192,  Alo, k0, tid);
    load_buf(stbase + 16384, Bhi, k0, tid);
    load_buf(stbase + 24576, Blo, k0, tid);
}

#define DECL_ACC(m, n) \
    float c##m##n##_0 = 0.f, c##m##n##_1 = 0.f, c##m##n##_2 = 0.f, c##m##n##_3 = 0.f
#define DECL_F(p, n) uint32_t p##n##_0, p##n##_1, p##n##_2, p##n##_3

// 3-term split MMA for one (mf, nf) pair at one k-half (B regs i0,i1)
#define DO_NF(m, n, i0, i1) \
    MMA_OP(c##m##n##_0, c##m##n##_1, c##m##n##_2, c##m##n##_3, \
           ah0, ah1, ah2, ah3, bh##n##_##i0, bh##n##_##i1); \
    MMA_OP(c##m##n##_0, c##m##n##_1, c##m##n##_2, c##m##n##_3, \
           al0, al1, al2, al3, bh##n##_##i0, bh##n##_##i1); \
    MMA_OP(c##m##n##_0, c##m##n##_1, c##m##n##_2, c##m##n##_3, \
           ah0, ah1, ah2, ah3, bl##n##_##i0, bl##n##_##i1)

#define DO_MF(m, AOFF, i0, i1) \
    LDSM_OP(ah0, ah1, ah2, ah3, Ah + (AOFF)); \
    LDSM_OP(al0, al1, al2, al3, Al + (AOFF)); \
    DO_NF(m, 0, i0, i1); DO_NF(m, 1, i0, i1); \
    DO_NF(m, 2, i0, i1); DO_NF(m, 3, i0, i1)

#define STORE_C(m, n) do { \
    int rr = wm * 64 + m * 16 + (lane >> 2); \
    int cc = wn * 32 + n * 8 + (lane & 3) * 2; \
    *(float2*)(Cp + (size_t)rr * ldc + cc) = make_float2(c##m##n##_0, c##m##n##_1); \
    *(float2*)(Cp + (size_t)(rr + 8) * ldc + cc) = make_float2(c##m##n##_2, c##m##n##_3); \
} while (0)

__device__ void gemm3_tile(
    const __nv_bfloat16* __restrict__ Ahi, const __nv_bfloat16* __restrict__ Alo,
    const __nv_bfloat16* __restrict__ Bhi, const __nv_bfloat16* __restrict__ Blo,
    float* __restrict__ Cp, int ldc)
{
    extern __shared__ char smem[];
    uint32_t sbase = smem_to_u32(smem);

    const int tid  = threadIdx.x;
    const int lane = tid & 31;
    const int wid  = tid >> 5;
    const int wm   = wid >> 2;     // 0..1 : 64-row slab
    const int wn   = wid & 3;      // 0..3 : 32-col slab

    DECL_ACC(0,0); DECL_ACC(0,1); DECL_ACC(0,2); DECL_ACC(0,3);
    DECL_ACC(1,0); DECL_ACC(1,1); DECL_ACC(1,2); DECL_ACC(1,3);
    DECL_ACC(2,0); DECL_ACC(2,1); DECL_ACC(2,2); DECL_ACC(2,3);
    DECL_ACC(3,0); DECL_ACC(3,1); DECL_ACC(3,2); DECL_ACC(3,3);

    const int NT = DIM / 32;   // 128 k-tiles

#pragma unroll
    for (int p = 0; p < GSTAGES - 1; p++) {
        g_load_stage(sbase, p, p * 32, Ahi, Alo, Bhi, Blo, tid);
        CP_COMMIT();
    }

    // ldmatrix offsets (scalars; relative to stage base)
    const int ar0 = wm * 64 + 0  + ((lane >> 3) & 1) * 8 + (lane & 7);
    const int ar1 = ar0 + 16, ar2 = ar0 + 32, ar3 = ar0 + 48;
    const uint32_t ao0_0 = sw_off(ar0, (lane >> 4)), ao0_1 = sw_off(ar0, 2 + (lane >> 4));
    const uint32_t ao1_0 = sw_off(ar1, (lane >> 4)), ao1_1 = sw_off(ar1, 2 + (lane >> 4));
    const uint32_t ao2_0 = sw_off(ar2, (lane >> 4)), ao2_1 = sw_off(ar2, 2 + (lane >> 4));
    const uint32_t ao3_0 = sw_off(ar3, (lane >> 4)), ao3_1 = sw_off(ar3, 2 + (lane >> 4));
    const uint32_t bo0 = sw_off(wn * 32 + 0  + (lane & 7), lane >> 3);
    const uint32_t bo1 = sw_off(wn * 32 + 8  + (lane & 7), lane >> 3);
    const uint32_t bo2 = sw_off(wn * 32 + 16 + (lane & 7), lane >> 3);
    const uint32_t bo3 = sw_off(wn * 32 + 24 + (lane & 7), lane >> 3);

    for (int i = 0; i < NT; i++) {
        if (i > 0) __syncthreads();            // readers done before overwrite
        int pf = i + GSTAGES - 1;
        if (pf < NT)
            g_load_stage(sbase, pf % GSTAGES, pf * 32, Ahi, Alo, Bhi, Blo, tid);
        CP_COMMIT();
        CP_WAIT(GSTAGES - 1);
        __syncthreads();

        uint32_t stb = sbase + (uint32_t)(i % GSTAGES) * GSTG_B;
        uint32_t Ah = stb, Al = stb + 8192, Bh = stb + 16384, Bl = stb + 24576;

        DECL_F(bh, 0); DECL_F(bh, 1); DECL_F(bh, 2); DECL_F(bh, 3);
        DECL_F(bl, 0); DECL_F(bl, 1); DECL_F(bl, 2); DECL_F(bl, 3);
        LDSM_OP(bh0_0, bh0_1, bh0_2, bh0_3, Bh + bo0);
        LDSM_OP(bh1_0, bh1_1, bh1_2, bh1_3, Bh + bo1);
        LDSM_OP(bh2_0, bh2_1, bh2_2, bh2_3, Bh + bo2);
        LDSM_OP(bh3_0, bh3_1, bh3_2, bh3_3, Bh + bo3);
        LDSM_OP(bl0_0, bl0_1, bl0_2, bl0_3, Bl + bo0);
        LDSM_OP(bl1_0, bl1_1, bl1_2, bl1_3, Bl + bo1);
        LDSM_OP(bl2_0, bl2_1, bl2_2, bl2_3, Bl + bo2);
        LDSM_OP(bl3_0, bl3_1, bl3_2, bl3_3, Bl + bo3);

        uint32_t ah0, ah1, ah2, ah3, al0, al1, al2, al3;
        // kh = 0 (B regs 0,1)
        DO_MF(0, ao0_0, 0, 1); DO_MF(1, ao1_0, 0, 1);
        DO_MF(2, ao2_0, 0, 1); DO_MF(3, ao3_0, 0, 1);
        // kh = 1 (B regs 2,3)
        DO_MF(0, ao0_1, 2, 3); DO_MF(1, ao1_1, 2, 3);
        DO_MF(2, ao2_1, 2, 3); DO_MF(3, ao3_1, 2, 3);
    }

    STORE_C(0,0); STORE_C(0,1); STORE_C(0,2); STORE_C(0,3);
    STORE_C(1,0); STORE_C(1,1); STORE_C(1,2); STORE_C(1,3);
    STORE_C(2,0); STORE_C(2,1); STORE_C(2,2); STORE_C(2,3);
    STORE_C(3,0); STORE_C(3,1); STORE_C(3,2); STORE_C(3,3);
}

__global__ __launch_bounds__(256, 1)
void qkv3_kernel()
{
    int nt = blockIdx.x, mt = blockIdx.y;
    int n0 = nt * 128, m0 = mt * 128;
    float* C; int ldc, col;
    if (nt < 32)      { C = g_Q; ldc = 4096; col = n0; }
    else if (nt < 40) { C = g_K; ldc = 1024; col = n0 - 4096; }
    else              { C = g_V; ldc = 1024; col = n0 - 5120; }
    gemm3_tile(g_Xhi + (size_t)m0 * DIM, g_Xlo + (size_t)m0 * DIM,
               g_Wqkvt_hi + (size_t)n0 * DIM, g_Wqkvt_lo + (size_t)n0 * DIM,
               C + (size_t)m0 * ldc + col, ldc);
}

__global__ __launch_bounds__(256, 1)
void out3_kernel(float* __restrict__ out)
{
    int n0 = (int)blockIdx.x * 128, m0 = (int)blockIdx.y * 128;
    gemm3_tile(g_Chi + (size_t)m0 * DIM, g_Clo + (size_t)m0 * DIM,
               g_Wot_hi + (size_t)n0 * DIM, g_Wot_lo + (size_t)n0 * DIM,
               out + (size_t)m0 * DIM + n0, DIM);
}

// ===========================================================================
// Fast exp on the FMA pipe
// ===========================================================================
__device__ __forceinline__ float fexp(float x) {
    float y = x * 1.4426950408889634f;
    y = fmaxf(y, -125.0f);
    float fl = floorf(y);
    float t = y - fl;
    float r = 1.5403530e-4f;
    r = fmaf(r, t, 1.3333558e-3f);
    r = fmaf(r, t, 9.6181291e-3f);
    r = fmaf(r, t, 5.5504109e-2f);
    r = fmaf(r, t, 2.4022651e-1f);
    r = fmaf(r, t, 6.9314718e-1f);
    r = fmaf(r, t, 1.0f);
    float s = __int_as_float(((int)fl + 127) << 23);
    return r * s;
}

// ===========================================================================
// RoPE in-place on g_Q and g_K
// ===========================================================================
__global__ void rope_kernel(const int* __restrict__ pos)
{
    int idx = blockIdx.x * blockDim.x + threadIdx.x;
    const int totq = SEQ * NH * 64;
    const int tot  = totq + SEQ * NKV * 64;
    if (idx >= tot) return;

    float* ptr;
    int nh;
    if (idx < totq) { ptr = g_Q; nh = NH; }
    else            { idx -= totq; ptr = g_K; nh = NKV; }

    int i = idx & 63;
    int h = (idx >> 6) % nh;
    int s = idx / (64 * nh);

    float p = (float)pos[s];
    float freq = (float)exp2(-(double)i * 0.31143075889569021);
    float t = p * freq;
    float sn, c;
    sincosf(t, &sn, &c);

    float* base = ptr + (size_t)s * (nh * HDIM) + h * HDIM + i;
    float x1 = base[0], x2 = base[64];
    base[0]  = x1 * c  - x2 * sn;
    base[64] = x1 * sn + x2 * c;
}

// ===========================================================================
// Flash attention, fp32; epilogue writes split bf16 (g_Chi/g_Clo)
// ===========================================================================
constexpr int ATTN_SMEM_FLOATS = 8192 * 3 + 4096 + 64;
constexpr int ATTN_SMEM = ATTN_SMEM_FLOATS * 4;

__global__ __launch_bounds__(256, 1)
void attn_kernel(const float* __restrict__ amask)
{
    extern __shared__ float sm[];
    float* Qs  = sm;
    float* Ks  = Qs + 8192;
    float* Vs  = Ks + 8192;
    float* Ps  = Vs + 8192;
    float* msk = Ps + 4096;

    const int h   = blockIdx.x;
    const int qt  = (int)gridDim.y - 1 - (int)blockIdx.y;
    const int g   = h >> 2;
    const int tid = threadIdx.x;
    const int tx  = tid & 15;
    const int ty  = tid >> 4;
    const int q0  = qt * 64;

    const int lrow = tid >> 5;
    const int slot = tid & 31;

    {
        const float scale = 0.08838834764831845f;
#pragma unroll
        for (int it = 0; it < 8; it++) {
            int row = lrow + it * 8;
            float4 v = *(const float4*)(g_Q + (size_t)(q0 + row) * (NH * HDIM)
                                        + h * HDIM + slot * 4);
            v.x *= scale; v.y *= scale; v.z *= scale; v.w *= scale;
            *(float4*)(Qs + row * 128 + ((slot ^ (row & 31)) << 2)) = v;
        }
    }

    float acc[4][8];
#pragma unroll
    for (int r = 0; r < 4; r++)
#pragma unroll
        for (int j = 0; j < 8; j++) acc[r][j] = 0.f;

    float mrow[4], lsum[4];
#pragma unroll
    for (int r = 0; r < 4; r++) { mrow[r] = -1e30f; lsum[r] = 0.f; }

    int qsw[4], ksw[4];
#pragma unroll
    for (int r = 0; r < 4; r++) {
        qsw[r] = (4 * ty + r) & 31;
        ksw[r] = (4 * tx + r) & 31;
    }

    const int nkt = qt + 1;
    for (int kt = 0; kt < nkt; kt++) {
        const int k0 = kt * 64;
        __syncthreads();

#pragma unroll
        for (int it = 0; it < 8; it++) {
            int row = lrow + it * 8;
            size_t goff = (size_t)(k0 + row) * (NKV * HDIM) + g * HDIM + slot * 4;
            float4 kv = *(const float4*)(g_K + goff);
            *(float4*)(Ks + row * 128 + ((slot ^ (row & 31)) << 2)) = kv;
            float4 vv = *(const float4*)(g_V + goff);
            *(float4*)(Vs + row * 128 + slot * 4) = vv;
        }
        if (tid < 64) msk[tid] = amask[k0 + tid];
        __syncthreads();

        float sc[4][4];
#pragma unroll
        for (int r = 0; r < 4; r++)
#pragma unroll
            for (int c = 0; c < 4; c++) sc[r][c] = 0.f;

#pragma unroll 4
        for (int d = 0; d < 32; d++) {
            float4 qv[4], kv[4];
#pragma unroll
            for (int r = 0; r < 4; r++)
                qv[r] = *(const float4*)(Qs + (4 * ty + r) * 128 + ((d ^ qsw[r]) << 2));
#pragma unroll
            for (int c = 0; c < 4; c++)
                kv[c] = *(const float4*)(Ks + (4 * tx + c) * 128 + ((d ^ ksw[c]) << 2));
#pragma unroll
            for (int r = 0; r < 4; r++)
#pragma unroll
                for (int c = 0; c < 4; c++) {
                    sc[r][c] = fmaf(qv[r].x, kv[c].x, sc[r][c]);
                    sc[r][c] = fmaf(qv[r].y, kv[c].y, sc[r][c]);
                    sc[r][c] = fmaf(qv[r].z, kv[c].z, sc[r][c]);
                    sc[r][c] = fmaf(qv[r].w, kv[c].w, sc[r][c]);
                }
        }

        const bool diag = (kt == qt);
#pragma unroll
        for (int c = 0; c < 4; c++) {
            float bias = (msk[4 * tx + c] > 0.f) ? 0.f : -1e30f;
#pragma unroll
            for (int r = 0; r < 4; r++) {
                float b = bias;
                if (diag && (4 * tx + c) > (4 * ty + r)) b = -1e30f;
                sc[r][c] += b;
            }
        }

        float alpha[4];
#pragma unroll
        for (int r = 0; r < 4; r++) {
            float mx = fmaxf(fmaxf(sc[r][0], sc[r][1]), fmaxf(sc[r][2], sc[r][3]));
#pragma unroll
            for (int off = 1; off < 16; off <<= 1)
                mx = fmaxf(mx, __shfl_xor_sync(0xffffffffu, mx, off, 16));
            float mnew = fmaxf(mrow[r], mx);
            float ssum = 0.f;
#pragma unroll
            for (int c = 0; c < 4; c++) {
                float p = fexp(sc[r][c] - mnew);
                sc[r][c] = p;
                ssum += p;
            }
#pragma unroll
            for (int off = 1; off < 16; off <<= 1)
                ssum += __shfl_xor_sync(0xffffffffu, ssum, off, 16);
            alpha[r] = fexp(mrow[r] - mnew);
            mrow[r] = mnew;
            lsum[r] = lsum[r] * alpha[r] + ssum;
        }

#pragma unroll
        for (int r = 0; r < 4; r++) {
            float4 pv = make_float4(sc[r][0], sc[r][1], sc[r][2], sc[r][3]);
            *(float4*)(Ps + (4 * ty + r) * 64 + 4 * tx) = pv;
        }
#pragma unroll
        for (int r = 0; r < 4; r++)
#pragma unroll
            for (int j = 0; j < 8; j++) acc[r][j] *= alpha[r];
        __syncthreads();

#pragma unroll 8
        for (int kk = 0; kk < 64; kk++) {
            float4 v0 = *(const float4*)(Vs + kk * 128 + tx * 8);
            float4 v1 = *(const float4*)(Vs + kk * 128 + tx * 8 + 4);
#pragma unroll
            for (int r = 0; r < 4; r++) {
                float p = Ps[(4 * ty + r) * 64 + kk];
                acc[r][0] = fmaf(p, v0.x, acc[r][0]);
                acc[r][1] = fmaf(p, v0.y, acc[r][1]);
                acc[r][2] = fmaf(p, v0.z, acc[r][2]);
                acc[r][3] = fmaf(p, v0.w, acc[r][3]);
                acc[r][4] = fmaf(p, v1.x, acc[r][4]);
                acc[r][5] = fmaf(p, v1.y, acc[r][5]);
                acc[r][6] = fmaf(p, v1.z, acc[r][6]);
                acc[r][7] = fmaf(p, v1.w, acc[r][7]);
            }
        }
    }

    // Normalize + split to bf16 hi/lo (feeds the HMMA output projection)
#pragma unroll
    for (int r = 0; r < 4; r++) {
        float inv = 1.0f / lsum[r];
        size_t o = (size_t)(q0 + 4 * ty + r) * DIM + h * HDIM + tx * 8;
#pragma unroll
        for (int j = 0; j < 8; j += 2) {
            float v0 = acc[r][j] * inv, v1 = acc[r][j + 1] * inv;
            __nv_bfloat16 h0, l0, h1, l1;
            split1(v0, h0, l0); split1(v1, h1, l1);
            *(__nv_bfloat162*)(g_Chi + o + j) = __nv_bfloat162(h0, h1);
            *(__nv_bfloat162*)(g_Clo + o + j) = __nv_bfloat162(l0, l1);
        }
    }
}

// ===========================================================================
extern "C" void kernel_launch(void* const* d_in, const int* in_sizes, int n_in,
                              void* d_out, int out_size)
{
    const float* X   = (const float*)d_in[0];
    const float* am  = (const float*)d_in[1];
    const int*   pos = (const int*)  d_in[2];
    const float* wq  = (const float*)d_in[3];
    const float* wk  = (const float*)d_in[4];
    const float* wv  = (const float*)d_in[5];
    const float* wo  = (const float*)d_in[6];
    float* out = (float*)d_out;

    (void)in_sizes; (void)n_in; (void)out_size;

    // 1. Split conversions
    xsplit_kernel<<<(SEQ * DIM / 4 + 255) / 256, 256>>>(X, SEQ * DIM / 4);
    wsplit_t_kernel<<<dim3(4096 / 32, 4096 / 32), 256>>>(wq, 4096, 0,    0);
    wsplit_t_kernel<<<dim3(1024 / 32, 4096 / 32), 256>>>(wk, 1024, 4096, 0);
    wsplit_t_kernel<<<dim3(1024 / 32, 4096 / 32), 256>>>(wv, 1024, 5120, 0);
    wsplit_t_kernel<<<dim3(4096 / 32, 4096 / 32), 256>>>(wo, 4096, 0,    1);

    // 2. QKV projection (HMMA split-bf16)
    cudaFuncSetAttribute((const void*)qkv3_kernel,
                         cudaFuncAttributeMaxDynamicSharedMemorySize, GEMM_SMEM);
    qkv3_kernel<<<dim3(48, 16), 256, GEMM_SMEM>>>();

    // 3. RoPE
    int tot = SEQ * (NH + NKV) * 64;
    rope_kernel<<<(tot + 255) / 256, 256>>>(pos);

    // 4. Flash attention (writes split bf16 context)
    cudaFuncSetAttribute((const void*)attn_kernel,
                         cudaFuncAttributeMaxDynamicSharedMemorySize, ATTN_SMEM);
    attn_kernel<<<dim3(NH, SEQ / 64), 256, ATTN_SMEM>>>(am);

    // 5. Output projection (HMMA split-bf16)
    cudaFuncSetAttribute((const void*)out3_kernel,
                         cudaFuncAttributeMaxDynamicSharedMemorySize, GEMM_SMEM);
    out3_kernel<<<dim3(32, 16), 256, GEMM_SMEM>>>(out);
}

// round 6
// speedup vs baseline: 1.5598x; 1.0010x over previous
#include <cuda_runtime.h>
#include <cuda_bf16.h>
#include <math.h>
#include <cstdint>

// Problem shape constants
constexpr int SEQ  = 2048;
constexpr int DIM  = 4096;
constexpr int NH   = 32;
constexpr int NKV  = 8;
constexpr int HDIM = 128;

// Scratch (device globals: allocation-free rule)
__device__ float g_Q[SEQ * NH * HDIM];     // 32 MB
__device__ float g_K[SEQ * NKV * HDIM];    // 8 MB
__device__ float g_V[SEQ * NKV * HDIM];    // 8 MB

// Split-bf16 operands (16B-aligned for cp.async)
__device__ __align__(256) __nv_bfloat16 g_Xhi[SEQ * DIM];
__device__ __align__(256) __nv_bfloat16 g_Xlo[SEQ * DIM];
__device__ __align__(256) __nv_bfloat16 g_Wqkvt_hi[6144 * DIM];   // [N=6144][K=4096] = W^T
__device__ __align__(256) __nv_bfloat16 g_Wqkvt_lo[6144 * DIM];
__device__ __align__(256) __nv_bfloat16 g_Wot_hi[DIM * DIM];      // [N=4096][K=4096] = Wo^T
__device__ __align__(256) __nv_bfloat16 g_Wot_lo[DIM * DIM];
__device__ __align__(256) __nv_bfloat16 g_Chi[SEQ * DIM];         // attention out (split)
__device__ __align__(256) __nv_bfloat16 g_Clo[SEQ * DIM];

// ===========================================================================
// PTX helpers (compute_100-baseline only: cp.async / ldmatrix / mma.sync)
// ===========================================================================
__device__ __forceinline__ uint32_t smem_to_u32(const void* smem_ptr) {
    uint32_t addr;
    asm("{ .reg .u64 tmp; cvta.to.shared.u64 tmp, %1; cvt.u32.u64 %0, tmp; }"
        : "=r"(addr) : "l"(smem_ptr));
    return addr;
}
__device__ __forceinline__ void cp16(uint32_t dst, const void* src) {
    asm volatile("cp.async.cg.shared.global [%0], [%1], 16;\n" :: "r"(dst), "l"(src));
}
#define CP_COMMIT() asm volatile("cp.async.commit_group;\n" ::: "memory")
#define CP_WAIT(n)  asm volatile("cp.async.wait_group %0;\n" :: "n"(n) : "memory")

// ALL fragment operands are named scalars — no arrays anywhere near inline asm
// (array-element asm operands defeated SROA -> 512 B/thread local -> 128 MiB
// local-pool growth -> harness mem-delta violation in R3/R4).
#define LDSM_OP(r0, r1, r2, r3, addr) \
    asm volatile("ldmatrix.sync.aligned.m8n8.x4.shared.b16 {%0,%1,%2,%3}, [%4];" \
        : "=r"(r0), "=r"(r1), "=r"(r2), "=r"(r3) : "r"(addr))

#define MMA_OP(d0, d1, d2, d3, A0, A1, A2, A3, B0, B1) \
    asm volatile("mma.sync.aligned.m16n8k16.row.col.f32.bf16.bf16.f32 " \
        "{%0,%1,%2,%3}, {%4,%5,%6,%7}, {%8,%9}, {%0,%1,%2,%3};" \
        : "+f"(d0), "+f"(d1), "+f"(d2), "+f"(d3) \
        : "r"(A0), "r"(A1), "r"(A2), "r"(A3), "r"(B0), "r"(B1))

// ===========================================================================
// Split conversions
// ===========================================================================
__device__ __forceinline__ void split1(float x, __nv_bfloat16& h, __nv_bfloat16& l) {
    h = __float2bfloat16(x);
    l = __float2bfloat16(x - __bfloat162float(h));
}

__global__ void xsplit_kernel(const float* __restrict__ X, int total4) {
    int idx = blockIdx.x * blockDim.x + threadIdx.x;
    if (idx >= total4) return;
    float4 v = ((const float4*)X)[idx];
    __nv_bfloat16 h0, h1, h2, h3, l0, l1, l2, l3;
    split1(v.x, h0, l0); split1(v.y, h1, l1);
    split1(v.z, h2, l2); split1(v.w, h3, l3);
    __nv_bfloat162* H2 = (__nv_bfloat162*)(g_Xhi + (size_t)idx * 4);
    __nv_bfloat162* L2 = (__nv_bfloat162*)(g_Xlo + (size_t)idx * 4);
    H2[0] = __nv_bfloat162(h0, h1); H2[1] = __nv_bfloat162(h2, h3);
    L2[0] = __nv_bfloat162(l0, l1); L2[1] = __nv_bfloat162(l2, l3);
}

// Transpose + split: W [K=4096, N] -> T[hi/lo] [dst_row_off + n, k]
__global__ void wsplit_t_kernel(const float* __restrict__ W, int N,
                                int dst_row_off, int which) { // 0 -> Wqkvt, 1 -> Wot
    __shared__ float s[32][33];
    int n0 = blockIdx.x * 32, k0 = blockIdx.y * 32;
    int lx = threadIdx.x & 31, ly = threadIdx.x >> 5;  // ly 0..7
#pragma unroll
    for (int r = 0; r < 4; r++) {
        int row = ly + r * 8;
        s[row][lx] = W[(size_t)(k0 + row) * N + n0 + lx];
    }
    __syncthreads();
    __nv_bfloat16* Hi = which ? g_Wot_hi : g_Wqkvt_hi;
    __nv_bfloat16* Lo = which ? g_Wot_lo : g_Wqkvt_lo;
#pragma unroll
    for (int r = 0; r < 4; r++) {
        int nrow = ly + r * 8;
        float x = s[lx][nrow];  // = W[k0+lx][n0+nrow]
        __nv_bfloat16 h, l; split1(x, h, l);
        size_t o = (size_t)(dst_row_off + n0 + nrow) * DIM + k0 + lx;
        Hi[o] = h; Lo[o] = l;
    }
}

// ===========================================================================
// HMMA split-bf16 GEMM: C[128,128] = (Ahi+Alo)[128,4096] @ (Bhi+Blo)^T
// Block 128x128x32, 8 warps (2x4), 3-stage cp.async pipeline. smem row =
// 32 bf16 = 4 x 16B chunks, swizzle chunk ^= (row>>1)&3.
// ===========================================================================
constexpr int GSTAGES   = 3;
constexpr int GSTG_B    = 32768;               // 4 buffers x 8KB
constexpr int GEMM_SMEM = GSTAGES * GSTG_B;    // 96 KB

__device__ __forceinline__ uint32_t sw_off(int row, int chunk) {
    return (uint32_t)(row * 64 + ((chunk ^ ((row >> 1) & 3)) << 4));
}

__device__ __forceinline__ void load_buf(uint32_t dbase, const __nv_bfloat16* g,
                                         int k0, int tid) {
#pragma unroll
    for (int j = 0; j < 2; j++) {
        int c   = tid * 2 + j;          // 0..511
        int row = c >> 2, ch = c & 3;
        cp16(dbase + sw_off(row, ch), g + (size_t)row * DIM + k0 + ch * 8);
    }
}

__device__ __forceinline__ void g_load_stage(
    uint32_t sbase, int s, int k0,
    const __nv_bfloat16* Ahi, const __nv_bfloat16* Alo,
    const __nv_bfloat16* Bhi, const __nv_bfloat16* Blo, int tid)
{
    uint32_t stbase = sbase + (uint32_t)s * GSTG_B;
    load_buf(stbase,         Ahi, k0, tid);
    load_buf(stbase + 8192,  Alo, k0, tid);
    load_buf(stbase + 16384, Bhi, k0, tid);
    load_buf(stbase + 24576, Blo, k0, tid);
}

#define DECL_ACC(m, n) \
    float c##m##n##_0 = 0.f, c##m##n##_1 = 0.f, c##m##n##_2 = 0.f, c##m##n##_3 = 0.f
#define DECL_F(p, n) uint32_t p##n##_0, p##n##_1, p##n##_2, p##n##_3

// 3-term split MMA for one (mf, nf) pair at one k-half (B regs i0,i1)
#define DO_NF(m, n, i0, i1) \
    MMA_OP(c##m##n##_0, c##m##n##_1, c##m##n##_2, c##m##n##_3, \
           ah0, ah1, ah2, ah3, bh##n##_##i0, bh##n##_##i1); \
    MMA_OP(c##m##n##_0, c##m##n##_1, c##m##n##_2, c##m##n##_3, \
           al0, al1, al2, al3, bh##n##_##i0, bh##n##_##i1); \
    MMA_OP(c##m##n##_0, c##m##n##_1, c##m##n##_2, c##m##n##_3, \
           ah0, ah1, ah2, ah3, bl##n##_##i0, bl##n##_##i1)

#define DO_MF(m, AOFF, i0, i1) \
    LDSM_OP(ah0, ah1, ah2, ah3, Ah + (AOFF)); \
    LDSM_OP(al0, al1, al2, al3, Al + (AOFF)); \
    DO_NF(m, 0, i0, i1); DO_NF(m, 1, i0, i1); \
    DO_NF(m, 2, i0, i1); DO_NF(m, 3, i0, i1)

#define STORE_C(m, n) do { \
    int rr = wm * 64 + m * 16 + (lane >> 2); \
    int cc = wn * 32 + n * 8 + (lane & 3) * 2; \
    *(float2*)(Cp + (size_t)rr * ldc + cc) = make_float2(c##m##n##_0, c##m##n##_1); \
    *(float2*)(Cp + (size_t)(rr + 8) * ldc + cc) = make_float2(c##m##n##_2, c##m##n##_3); \
} while (0)

__device__ void gemm3_tile(
    const __nv_bfloat16* __restrict__ Ahi, const __nv_bfloat16* __restrict__ Alo,
    const __nv_bfloat16* __restrict__ Bhi, const __nv_bfloat16* __restrict__ Blo,
    float* __restrict__ Cp, int ldc)
{
    extern __shared__ char smem[];
    uint32_t sbase = smem_to_u32(smem);

    const int tid  = threadIdx.x;
    const int lane = tid & 31;
    const int wid  = tid >> 5;
    const int wm   = wid >> 2;     // 0..1 : 64-row slab
    const int wn   = wid & 3;      // 0..3 : 32-col slab

    DECL_ACC(0,0); DECL_ACC(0,1); DECL_ACC(0,2); DECL_ACC(0,3);
    DECL_ACC(1,0); DECL_ACC(1,1); DECL_ACC(1,2); DECL_ACC(1,3);
    DECL_ACC(2,0); DECL_ACC(2,1); DECL_ACC(2,2); DECL_ACC(2,3);
    DECL_ACC(3,0); DECL_ACC(3,1); DECL_ACC(3,2); DECL_ACC(3,3);

    const int NT = DIM / 32;   // 128 k-tiles

#pragma unroll
    for (int p = 0; p < GSTAGES - 1; p++) {
        g_load_stage(sbase, p, p * 32, Ahi, Alo, Bhi, Blo, tid);
        CP_COMMIT();
    }

    // ldmatrix offsets (scalars; relative to stage base)
    const int ar0 = wm * 64 + 0  + ((lane >> 3) & 1) * 8 + (lane & 7);
    const int ar1 = ar0 + 16, ar2 = ar0 + 32, ar3 = ar0 + 48;
    const uint32_t ao0_0 = sw_off(ar0, (lane >> 4)), ao0_1 = sw_off(ar0, 2 + (lane >> 4));
    const uint32_t ao1_0 = sw_off(ar1, (lane >> 4)), ao1_1 = sw_off(ar1, 2 + (lane >> 4));
    const uint32_t ao2_0 = sw_off(ar2, (lane >> 4)), ao2_1 = sw_off(ar2, 2 + (lane >> 4));
    const uint32_t ao3_0 = sw_off(ar3, (lane >> 4)), ao3_1 = sw_off(ar3, 2 + (lane >> 4));
    const uint32_t bo0 = sw_off(wn * 32 + 0  + (lane & 7), lane >> 3);
    const uint32_t bo1 = sw_off(wn * 32 + 8  + (lane & 7), lane >> 3);
    const uint32_t bo2 = sw_off(wn * 32 + 16 + (lane & 7), lane >> 3);
    const uint32_t bo3 = sw_off(wn * 32 + 24 + (lane & 7), lane >> 3);

    for (int i = 0; i < NT; i++) {
        if (i > 0) __syncthreads();            // readers done before overwrite
        int pf = i + GSTAGES - 1;
        if (pf < NT)
            g_load_stage(sbase, pf % GSTAGES, pf * 32, Ahi, Alo, Bhi, Blo, tid);
        CP_COMMIT();
        CP_WAIT(GSTAGES - 1);
        __syncthreads();

        uint32_t stb = sbase + (uint32_t)(i % GSTAGES) * GSTG_B;
        uint32_t Ah = stb, Al = stb + 8192, Bh = stb + 16384, Bl = stb + 24576;

        DECL_F(bh, 0); DECL_F(bh, 1); DECL_F(bh, 2); DECL_F(bh, 3);
        DECL_F(bl, 0); DECL_F(bl, 1); DECL_F(bl, 2); DECL_F(bl, 3);
        LDSM_OP(bh0_0, bh0_1, bh0_2, bh0_3, Bh + bo0);
        LDSM_OP(bh1_0, bh1_1, bh1_2, bh1_3, Bh + bo1);
        LDSM_OP(bh2_0, bh2_1, bh2_2, bh2_3, Bh + bo2);
        LDSM_OP(bh3_0, bh3_1, bh3_2, bh3_3, Bh + bo3);
        LDSM_OP(bl0_0, bl0_1, bl0_2, bl0_3, Bl + bo0);
        LDSM_OP(bl1_0, bl1_1, bl1_2, bl1_3, Bl + bo1);
        LDSM_OP(bl2_0, bl2_1, bl2_2, bl2_3, Bl + bo2);
        LDSM_OP(bl3_0, bl3_1, bl3_2, bl3_3, Bl + bo3);

        uint32_t ah0, ah1, ah2, ah3, al0, al1, al2, al3;
        // kh = 0 (B regs 0,1)
        DO_MF(0, ao0_0, 0, 1); DO_MF(1, ao1_0, 0, 1);
        DO_MF(2, ao2_0, 0, 1); DO_MF(3, ao3_0, 0, 1);
        // kh = 1 (B regs 2,3)
        DO_MF(0, ao0_1, 2, 3); DO_MF(1, ao1_1, 2, 3);
        DO_MF(2, ao2_1, 2, 3); DO_MF(3, ao3_1, 2, 3);
    }

    STORE_C(0,0); STORE_C(0,1); STORE_C(0,2); STORE_C(0,3);
    STORE_C(1,0); STORE_C(1,1); STORE_C(1,2); STORE_C(1,3);
    STORE_C(2,0); STORE_C(2,1); STORE_C(2,2); STORE_C(2,3);
    STORE_C(3,0); STORE_C(3,1); STORE_C(3,2); STORE_C(3,3);
}

__global__ __launch_bounds__(256, 1)
void qkv3_kernel()
{
    int nt = blockIdx.x, mt = blockIdx.y;
    int n0 = nt * 128, m0 = mt * 128;
    float* C; int ldc, col;
    if (nt < 32)      { C = g_Q; ldc = 4096; col = n0; }
    else if (nt < 40) { C = g_K; ldc = 1024; col = n0 - 4096; }
    else              { C = g_V; ldc = 1024; col = n0 - 5120; }
    gemm3_tile(g_Xhi + (size_t)m0 * DIM, g_Xlo + (size_t)m0 * DIM,
               g_Wqkvt_hi + (size_t)n0 * DIM, g_Wqkvt_lo + (size_t)n0 * DIM,
               C + (size_t)m0 * ldc + col, ldc);
}

__global__ __launch_bounds__(256, 1)
void out3_kernel(float* __restrict__ out)
{
    int n0 = (int)blockIdx.x * 128, m0 = (int)blockIdx.y * 128;
    gemm3_tile(g_Chi + (size_t)m0 * DIM, g_Clo + (size_t)m0 * DIM,
               g_Wot_hi + (size_t)n0 * DIM, g_Wot_lo + (size_t)n0 * DIM,
               out + (size_t)m0 * DIM + n0, DIM);
}

// ===========================================================================
// Fast exp on the FMA pipe
// ===========================================================================
__device__ __forceinline__ float fexp(float x) {
    float y = x * 1.4426950408889634f;
    y = fmaxf(y, -125.0f);
    float fl = floorf(y);
    float t = y - fl;
    float r = 1.5403530e-4f;
    r = fmaf(r, t, 1.3333558e-3f);
    r = fmaf(r, t, 9.6181291e-3f);
    r = fmaf(r, t, 5.5504109e-2f);
    r = fmaf(r, t, 2.4022651e-1f);
    r = fmaf(r, t, 6.9314718e-1f);
    r = fmaf(r, t, 1.0f);
    float s = __int_as_float(((int)fl + 127) << 23);
    return r * s;
}

// ===========================================================================
// RoPE in-place on g_Q and g_K
// ===========================================================================
__global__ void rope_kernel(const int* __restrict__ pos)
{
    int idx = blockIdx.x * blockDim.x + threadIdx.x;
    const int totq = SEQ * NH * 64;
    const int tot  = totq + SEQ * NKV * 64;
    if (idx >= tot) return;

    float* ptr;
    int nh;
    if (idx < totq) { ptr = g_Q; nh = NH; }
    else            { idx -= totq; ptr = g_K; nh = NKV; }

    int i = idx & 63;
    int h = (idx >> 6) % nh;
    int s = idx / (64 * nh);

    float p = (float)pos[s];
    float freq = (float)exp2(-(double)i * 0.31143075889569021);
    float t = p * freq;
    float sn, c;
    sincosf(t, &sn, &c);

    float* base = ptr + (size_t)s * (nh * HDIM) + h * HDIM + i;
    float x1 = base[0], x2 = base[64];
    base[0]  = x1 * c  - x2 * sn;
    base[64] = x1 * sn + x2 * c;
}

// ===========================================================================
// Flash attention, fp32; epilogue writes split bf16 (g_Chi/g_Clo)
// ===========================================================================
constexpr int ATTN_SMEM_FLOATS = 8192 * 3 + 4096 + 64;
constexpr int ATTN_SMEM = ATTN_SMEM_FLOATS * 4;

__global__ __launch_bounds__(256, 1)
void attn_kernel(const float* __restrict__ amask)
{
    extern __shared__ float sm[];
    float* Qs  = sm;
    float* Ks  = Qs + 8192;
    float* Vs  = Ks + 8192;
    float* Ps  = Vs + 8192;
    float* msk = Ps + 4096;

    const int h   = blockIdx.x;
    const int qt  = (int)gridDim.y - 1 - (int)blockIdx.y;
    const int g   = h >> 2;
    const int tid = threadIdx.x;
    const int tx  = tid & 15;
    const int ty  = tid >> 4;
    const int q0  = qt * 64;

    const int lrow = tid >> 5;
    const int slot = tid & 31;

    {
        const float scale = 0.08838834764831845f;
#pragma unroll
        for (int it = 0; it < 8; it++) {
            int row = lrow + it * 8;
            float4 v = *(const float4*)(g_Q + (size_t)(q0 + row) * (NH * HDIM)
                                        + h * HDIM + slot * 4);
            v.x *= scale; v.y *= scale; v.z *= scale; v.w *= scale;
            *(float4*)(Qs + row * 128 + ((slot ^ (row & 31)) << 2)) = v;
        }
    }

    float acc[4][8];
#pragma unroll
    for (int r = 0; r < 4; r++)
#pragma unroll
        for (int j = 0; j < 8; j++) acc[r][j] = 0.f;

    float mrow[4], lsum[4];
#pragma unroll
    for (int r = 0; r < 4; r++) { mrow[r] = -1e30f; lsum[r] = 0.f; }

    int qsw[4], ksw[4];
#pragma unroll
    for (int r = 0; r < 4; r++) {
        qsw[r] = (4 * ty + r) & 31;
        ksw[r] = (4 * tx + r) & 31;
    }

    const int nkt = qt + 1;
    for (int kt = 0; kt < nkt; kt++) {
        const int k0 = kt * 64;
        __syncthreads();

#pragma unroll
        for (int it = 0; it < 8; it++) {
            int row = lrow + it * 8;
            size_t goff = (size_t)(k0 + row) * (NKV * HDIM) + g * HDIM + slot * 4;
            float4 kv = *(const float4*)(g_K + goff);
            *(float4*)(Ks + row * 128 + ((slot ^ (row & 31)) << 2)) = kv;
            float4 vv = *(const float4*)(g_V + goff);
            *(float4*)(Vs + row * 128 + slot * 4) = vv;
        }
        if (tid < 64) msk[tid] = amask[k0 + tid];
        __syncthreads();

        float sc[4][4];
#pragma unroll
        for (int r = 0; r < 4; r++)
#pragma unroll
            for (int c = 0; c < 4; c++) sc[r][c] = 0.f;

#pragma unroll 4
        for (int d = 0; d < 32; d++) {
            float4 qv[4], kv[4];
#pragma unroll
            for (int r = 0; r < 4; r++)
                qv[r] = *(const float4*)(Qs + (4 * ty + r) * 128 + ((d ^ qsw[r]) << 2));
#pragma unroll
            for (int c = 0; c < 4; c++)
                kv[c] = *(const float4*)(Ks + (4 * tx + c) * 128 + ((d ^ ksw[c]) << 2));
#pragma unroll
            for (int r = 0; r < 4; r++)
#pragma unroll
                for (int c = 0; c < 4; c++) {
                    sc[r][c] = fmaf(qv[r].x, kv[c].x, sc[r][c]);
                    sc[r][c] = fmaf(qv[r].y, kv[c].y, sc[r][c]);
                    sc[r][c] = fmaf(qv[r].z, kv[c].z, sc[r][c]);
                    sc[r][c] = fmaf(qv[r].w, kv[c].w, sc[r][c]);
                }
        }

        const bool diag = (kt == qt);
#pragma unroll
        for (int c = 0; c < 4; c++) {
            float bias = (msk[4 * tx + c] > 0.f) ? 0.f : -1e30f;
#pragma unroll
            for (int r = 0; r < 4; r++) {
                float b = bias;
                if (diag && (4 * tx + c) > (4 * ty + r)) b = -1e30f;
                sc[r][c] += b;
            }
        }

        float alpha[4];
#pragma unroll
        for (int r = 0; r < 4; r++) {
            float mx = fmaxf(fmaxf(sc[r][0], sc[r][1]), fmaxf(sc[r][2], sc[r][3]));
#pragma unroll
            for (int off = 1; off < 16; off <<= 1)
                mx = fmaxf(mx, __shfl_xor_sync(0xffffffffu, mx, off, 16));
            float mnew = fmaxf(mrow[r], mx);
            float ssum = 0.f;
#pragma unroll
            for (int c = 0; c < 4; c++) {
                float p = fexp(sc[r][c] - mnew);
                sc[r][c] = p;
                ssum += p;
            }
#pragma unroll
            for (int off = 1; off < 16; off <<= 1)
                ssum += __shfl_xor_sync(0xffffffffu, ssum, off, 16);
            alpha[r] = fexp(mrow[r] - mnew);
            mrow[r] = mnew;
            lsum[r] = lsum[r] * alpha[r] + ssum;
        }

#pragma unroll
        for (int r = 0; r < 4; r++) {
            float4 pv = make_float4(sc[r][0], sc[r][1], sc[r][2], sc[r][3]);
            *(float4*)(Ps + (4 * ty + r) * 64 + 4 * tx) = pv;
        }
#pragma unroll
        for (int r = 0; r < 4; r++)
#pragma unroll
            for (int j = 0; j < 8; j++) acc[r][j] *= alpha[r];
        __syncthreads();

#pragma unroll 8
        for (int kk = 0; kk < 64; kk++) {
            float4 v0 = *(const float4*)(Vs + kk * 128 + tx * 8);
            float4 v1 = *(const float4*)(Vs + kk * 128 + tx * 8 + 4);
#pragma unroll
            for (int r = 0; r < 4; r++) {
                float p = Ps[(4 * ty + r) * 64 + kk];
                acc[r][0] = fmaf(p, v0.x, acc[r][0]);
                acc[r][1] = fmaf(p, v0.y, acc[r][1]);
                acc[r][2] = fmaf(p, v0.z, acc[r][2]);
                acc[r][3] = fmaf(p, v0.w, acc[r][3]);
                acc[r][4] = fmaf(p, v1.x, acc[r][4]);
                acc[r][5] = fmaf(p, v1.y, acc[r][5]);
                acc[r][6] = fmaf(p, v1.z, acc[r][6]);
                acc[r][7] = fmaf(p, v1.w, acc[r][7]);
            }
        }
    }

    // Normalize + split to bf16 hi/lo (feeds the HMMA output projection)
#pragma unroll
    for (int r = 0; r < 4; r++) {
        float inv = 1.0f / lsum[r];
        size_t o = (size_t)(q0 + 4 * ty + r) * DIM + h * HDIM + tx * 8;
#pragma unroll
        for (int j = 0; j < 8; j += 2) {
            float v0 = acc[r][j] * inv, v1 = acc[r][j + 1] * inv;
            __nv_bfloat16 h0, l0, h1, l1;
            split1(v0, h0, l0); split1(v1, h1, l1);
            *(__nv_bfloat162*)(g_Chi + o + j) = __nv_bfloat162(h0, h1);
            *(__nv_bfloat162*)(g_Clo + o + j) = __nv_bfloat162(l0, l1);
        }
    }
}

// ===========================================================================
extern "C" void kernel_launch(void* const* d_in, const int* in_sizes, int n_in,
                              void* d_out, int out_size)
{
    const float* X   = (const float*)d_in[0];
    const float* am  = (const float*)d_in[1];
    const int*   pos = (const int*)  d_in[2];
    const float* wq  = (const float*)d_in[3];
    const float* wk  = (const float*)d_in[4];
    const float* wv  = (const float*)d_in[5];
    const float* wo  = (const float*)d_in[6];
    float* out = (float*)d_out;

    (void)in_sizes; (void)n_in; (void)out_size;

    // 1. Split conversions
    xsplit_kernel<<<(SEQ * DIM / 4 + 255) / 256, 256>>>(X, SEQ * DIM / 4);
    wsplit_t_kernel<<<dim3(4096 / 32, 4096 / 32), 256>>>(wq, 4096, 0,    0);
    wsplit_t_kernel<<<dim3(1024 / 32, 4096 / 32), 256>>>(wk, 1024, 4096, 0);
    wsplit_t_kernel<<<dim3(1024 / 32, 4096 / 32), 256>>>(wv, 1024, 5120, 0);
    wsplit_t_kernel<<<dim3(4096 / 32, 4096 / 32), 256>>>(wo, 4096, 0,    1);

    // 2. QKV projection (HMMA split-bf16)
    cudaFuncSetAttribute((const void*)qkv3_kernel,
                         cudaFuncAttributeMaxDynamicSharedMemorySize, GEMM_SMEM);
    qkv3_kernel<<<dim3(48, 16), 256, GEMM_SMEM>>>();

    // 3. RoPE
    int tot = SEQ * (NH + NKV) * 64;
    rope_kernel<<<(tot + 255) / 256, 256>>>(pos);

    // 4. Flash attention (writes split bf16 context)
    cudaFuncSetAttribute((const void*)attn_kernel,
                         cudaFuncAttributeMaxDynamicSharedMemorySize, ATTN_SMEM);
    attn_kernel<<<dim3(NH, SEQ / 64), 256, ATTN_SMEM>>>(am);

    // 5. Output projection (HMMA split-bf16)
    cudaFuncSetAttribute((const void*)out3_kernel,
                         cudaFuncAttributeMaxDynamicSharedMemorySize, GEMM_SMEM);
    out3_kernel<<<dim3(32, 16), 256, GEMM_SMEM>>>(out);
}